// round 7
// baseline (speedup 1.0000x reference)
#include <cuda_runtime.h>
#include <math.h>

typedef unsigned long long ull;

// ---------------------------------------------------------------------------
// packed fp32x2 helpers (Blackwell FFMA2)
// ---------------------------------------------------------------------------
#define FMA2(d, a, b, c) \
    asm("fma.rn.f32x2 %0, %1, %2, %3;" : "=l"(d) : "l"(a), "l"(b), "l"(c))

static __device__ __forceinline__ ull pack2(float lo, float hi) {
    ull r; asm("mov.b64 %0, {%1, %2};" : "=l"(r) : "f"(lo), "f"(hi)); return r;
}
static __device__ __forceinline__ float2 unpack2(ull v) {
    float2 r; asm("mov.b64 {%0, %1}, %2;" : "=f"(r.x), "=f"(r.y) : "l"(v)); return r;
}
static __device__ __forceinline__ ull lds64(const float* p) {
    return *reinterpret_cast<const ull*>(p);
}

// Scratch: per-image softmax probabilities (1024 batches * 16 digits * 10)
__device__ float g_probs[1024 * 16 * 10];

// ---------------------------------------------------------------------------
// shared memory layout (float offsets)
// ---------------------------------------------------------------------------
#define OFF_DW1T  0        // [120][260]  transposed dw1, 16B-aligned rows
#define DW1_STR   260
#define OFF_DW2T  31200    // [84][124]   transposed dw2, 16B-aligned rows
#define DW2_STR   124
#define OFF_DW3   41616    // 840
#define OFF_W1P   42456    // [25][8]  conv1 weights, 6 ch + 2 pad per tap
#define OFF_W2X   42656    // 2400: [(pk*3+ip)][32] = [cg][i-parity][out-parity]
#define OFF_B1    45056    // 8
#define OFF_B2    45064    // 16
#define OFF_DB1   45080    // 120
#define OFF_DB2   45200    // 88
#define OFF_DB3   45288    // 12
#define OFF_IMG   45300    // [4][784]
#define OFF_P1T   48436    // [4][6][12][24]  pooled conv1, dup pairs
#define P1_IMG_STR 1728
#define OFF_P2    55348    // [4][264]
#define P2_STR    264
#define OFF_FC1   56404    // [4][120]
#define OFF_FC2   56884    // [4][88]
#define OFF_LOG   57236    // [4][12]
#define SMEM_FLOATS 57284  // = 229,136 bytes

// ---------------------------------------------------------------------------
// Kernel 1: persistent fused LeNet. 148 CTAs x 512 threads, CTA-wide phases
// over batches of 4 images. Weight reads amortized across outputs (conv2)
// and across images (fc1/fc2).
// ---------------------------------------------------------------------------
__global__ void __launch_bounds__(512, 1) cnn_kernel(
    const float* __restrict__ inputs,
    const float* __restrict__ cw1, const float* __restrict__ cb1,
    const float* __restrict__ cw2, const float* __restrict__ cb2,
    const float* __restrict__ dw1, const float* __restrict__ db1,
    const float* __restrict__ dw2, const float* __restrict__ db2,
    const float* __restrict__ dw3, const float* __restrict__ db3,
    int nimg)
{
    extern __shared__ float sm[];
    const int tid = threadIdx.x;

    // ---- one-time weight staging ----
    for (int idx = tid; idx < 256 * 120; idx += 512) {
        int k = idx / 120, j = idx % 120;               // dw1[k][j]
        sm[OFF_DW1T + j * DW1_STR + k] = dw1[idx];
    }
    for (int idx = tid; idx < 120 * 84; idx += 512) {
        int k = idx / 84, j = idx % 84;                 // dw2[k][j]
        sm[OFF_DW2T + j * DW2_STR + k] = dw2[idx];
    }
    for (int idx = tid; idx < 840; idx += 512) sm[OFF_DW3 + idx] = dw3[idx];
    for (int idx = tid; idx < 150; idx += 512) {        // w1p: [pk][8]
        int pk = idx / 6, c = idx % 6;
        sm[OFF_W1P + pk * 8 + c] = cw1[idx];
    }
    for (int idx = tid; idx < 2400; idx += 512) {       // w2x interleaved
        int p = idx >> 4, ch = idx & 15;
        int pk = p / 6, i = p % 6;
        sm[OFF_W2X + (pk * 3 + (i >> 1)) * 32 + (ch >> 1) * 4 + (i & 1) * 2 + (ch & 1)]
            = cw2[idx];
    }
    if (tid < 6)   sm[OFF_B1  + tid] = cb1[tid];
    if (tid < 16)  sm[OFF_B2  + tid] = cb2[tid];
    if (tid < 120) sm[OFF_DB1 + tid] = db1[tid];
    if (tid < 84)  sm[OFF_DB2 + tid] = db2[tid];
    if (tid < 10)  sm[OFF_DB3 + tid] = db3[tid];

    // ---- prologue: load first batch of 4 images ----
    {
        const int b0 = blockIdx.x * 4;
        if (b0 < nimg) {
            const float4* iv = reinterpret_cast<const float4*>(inputs + (size_t)b0 * 784);
            float4* ov = reinterpret_cast<float4*>(sm + OFF_IMG);
            for (int i = tid; i < 784; i += 512) ov[i] = iv[i];
        }
    }
    __syncthreads();

    for (int base = blockIdx.x * 4; base < nimg; base += gridDim.x * 4) {

        // =========== conv1 (5x5->6) + relu + pool. 288 threads ===========
        if (tid < 288) {
            const int img = tid / 72;
            const int r72 = tid % 72;
            const int py = r72 / 6, xg = r72 % 6, x0 = 4 * xg;
            const float* ibase = sm + OFF_IMG + img * 784 + 2 * py * 28 + x0;
            float* s_p1 = sm + OFF_P1T + img * P1_IMG_STR;

            ull bp[3];
            #pragma unroll
            for (int cp = 0; cp < 3; cp++)
                bp[cp] = pack2(sm[OFF_B1 + 2 * cp], sm[OFF_B1 + 2 * cp + 1]);
            ull acc[2][4][3];
            #pragma unroll
            for (int dy = 0; dy < 2; dy++)
                #pragma unroll
                for (int dx = 0; dx < 4; dx++)
                    #pragma unroll
                    for (int cp = 0; cp < 3; cp++) acc[dy][dx][cp] = bp[cp];

            #pragma unroll
            for (int r = 0; r < 6; r++) {
                float4 v0 = *reinterpret_cast<const float4*>(ibase + r * 28);
                float4 v1 = *reinterpret_cast<const float4*>(ibase + r * 28 + 4);
                ull ap[8];
                ap[0] = pack2(v0.x, v0.x); ap[1] = pack2(v0.y, v0.y);
                ap[2] = pack2(v0.z, v0.z); ap[3] = pack2(v0.w, v0.w);
                ap[4] = pack2(v1.x, v1.x); ap[5] = pack2(v1.y, v1.y);
                ap[6] = pack2(v1.z, v1.z); ap[7] = pack2(v1.w, v1.w);
                #pragma unroll
                for (int dy = 0; dy < 2; dy++) {
                    const int ky = r - dy;
                    if (ky < 0 || ky > 4) continue;
                    #pragma unroll
                    for (int kx = 0; kx < 5; kx++) {
                        const float* wp = sm + OFF_W1P + (ky * 5 + kx) * 8;
                        ulonglong2 w01 = *reinterpret_cast<const ulonglong2*>(wp);
                        ull w2 = lds64(wp + 4);
                        #pragma unroll
                        for (int dx = 0; dx < 4; dx++) {
                            FMA2(acc[dy][dx][0], ap[kx + dx], w01.x, acc[dy][dx][0]);
                            FMA2(acc[dy][dx][1], ap[kx + dx], w01.y, acc[dy][dx][1]);
                            FMA2(acc[dy][dx][2], ap[kx + dx], w2,    acc[dy][dx][2]);
                        }
                    }
                }
            }
            #pragma unroll
            for (int cp = 0; cp < 3; cp++) {
                #pragma unroll
                for (int dxp = 0; dxp < 2; dxp++) {
                    float2 a0 = unpack2(acc[0][2 * dxp][cp]);
                    float2 a1 = unpack2(acc[0][2 * dxp + 1][cp]);
                    float2 b0 = unpack2(acc[1][2 * dxp][cp]);
                    float2 b1 = unpack2(acc[1][2 * dxp + 1][cp]);
                    float m0 = fmaxf(fmaxf(fmaxf(a0.x, a1.x), fmaxf(b0.x, b1.x)), 0.0f);
                    float m1 = fmaxf(fmaxf(fmaxf(a0.y, a1.y), fmaxf(b0.y, b1.y)), 0.0f);
                    const int px = 2 * xg + dxp;
                    *reinterpret_cast<ull*>(s_p1 + ((2 * cp)     * 12 + py) * 24 + 2 * px) = pack2(m0, m0);
                    *reinterpret_cast<ull*>(s_p1 + ((2 * cp + 1) * 12 + py) * 24 + 2 * px) = pack2(m1, m1);
                }
            }
        }
        __syncthreads();

        // =========== conv2 (5x5x6->16) + relu + pool. 128 threads =========
        // thread = (img, py 0..3, cg 0..7): conv rows 2py..2py+1, ALL 8 conv
        // columns (acc[2][8]), channels 2cg..2cg+1. Each weight LDS.128 feeds
        // 8 columns -> weight smem traffic halved vs r6.
        if (tid < 128) {
            const int img = tid >> 5;
            const int u   = tid & 31;
            const int py = u >> 3, cg = u & 7;
            const float* pbase = sm + OFF_P1T + img * P1_IMG_STR;
            const float* wbase = sm + OFF_W2X + cg * 4;

            ull bp = lds64(sm + OFF_B2 + 2 * cg);
            ull acc[2][8];
            #pragma unroll
            for (int dy = 0; dy < 2; dy++)
                #pragma unroll
                for (int dx = 0; dx < 8; dx++) acc[dy][dx] = bp;

            #pragma unroll
            for (int r = 0; r < 6; r++) {
                const int iy = 2 * py + r;
                #pragma unroll
                for (int ip = 0; ip < 3; ip++) {
                    const float* r0 = pbase + (2 * ip) * 288 + iy * 24;
                    const float* r1 = r0 + 288;
                    ull ap0[12], ap1[12];
                    #pragma unroll
                    for (int jj = 0; jj < 6; jj++) {
                        ulonglong2 t0 = *reinterpret_cast<const ulonglong2*>(r0 + 4 * jj);
                        ap0[2 * jj] = t0.x; ap0[2 * jj + 1] = t0.y;
                        ulonglong2 t1 = *reinterpret_cast<const ulonglong2*>(r1 + 4 * jj);
                        ap1[2 * jj] = t1.x; ap1[2 * jj + 1] = t1.y;
                    }
                    #pragma unroll
                    for (int dy = 0; dy < 2; dy++) {
                        const int ky = r - dy;
                        if (ky < 0 || ky > 4) continue;
                        #pragma unroll
                        for (int kx = 0; kx < 5; kx++) {
                            ulonglong2 w = *reinterpret_cast<const ulonglong2*>(
                                wbase + ((ky * 5 + kx) * 3 + ip) * 32);
                            #pragma unroll
                            for (int dx = 0; dx < 8; dx++) {
                                FMA2(acc[dy][dx], ap0[kx + dx], w.x, acc[dy][dx]);
                                FMA2(acc[dy][dx], ap1[kx + dx], w.y, acc[dy][dx]);
                            }
                        }
                    }
                }
            }
            float* s_p2 = sm + OFF_P2 + img * P2_STR;
            #pragma unroll
            for (int pxp = 0; pxp < 4; pxp++) {
                float2 a0 = unpack2(acc[0][2 * pxp]);
                float2 a1 = unpack2(acc[0][2 * pxp + 1]);
                float2 b0 = unpack2(acc[1][2 * pxp]);
                float2 b1 = unpack2(acc[1][2 * pxp + 1]);
                float m0 = fmaxf(fmaxf(fmaxf(a0.x, a1.x), fmaxf(b0.x, b1.x)), 0.0f);
                float m1 = fmaxf(fmaxf(fmaxf(a0.y, a1.y), fmaxf(b0.y, b1.y)), 0.0f);
                *reinterpret_cast<ull*>(s_p2 + (py * 4 + pxp) * 16 + 2 * cg) = pack2(m0, m1);
            }
        } else {
            // prefetch next batch of 4 images (img smem dead after conv1)
            const int nb = base + gridDim.x * 4;
            if (nb < nimg) {
                const float4* iv = reinterpret_cast<const float4*>(inputs + (size_t)nb * 784);
                float4* ov = reinterpret_cast<float4*>(sm + OFF_IMG);
                for (int i = tid - 128; i < 784; i += 384) ov[i] = iv[i];
            }
        }
        __syncthreads();

        // ====== fc1: 256 -> 120, relu. 120 threads, 4 images each ======
        // Weight row loaded once, applied to all 4 in-flight images.
        if (tid < 120) {
            const int j = tid;
            const float* wr = sm + OFF_DW1T + j * DW1_STR;
            ull a0[4], a1[4];
            #pragma unroll
            for (int img = 0; img < 4; img++) { a0[img] = pack2(0.f, 0.f); a1[img] = a0[img]; }
            #pragma unroll 4
            for (int k = 0; k < 256; k += 4) {
                ulonglong2 wv = *reinterpret_cast<const ulonglong2*>(wr + k);
                #pragma unroll
                for (int img = 0; img < 4; img++) {
                    ulonglong2 av = *reinterpret_cast<const ulonglong2*>(
                        sm + OFF_P2 + img * P2_STR + k);
                    FMA2(a0[img], av.x, wv.x, a0[img]);
                    FMA2(a1[img], av.y, wv.y, a1[img]);
                }
            }
            #pragma unroll
            for (int img = 0; img < 4; img++) {
                float2 s0 = unpack2(a0[img]), s1 = unpack2(a1[img]);
                float v = s0.x + s0.y + s1.x + s1.y + sm[OFF_DB1 + j];
                sm[OFF_FC1 + img * 120 + j] = fmaxf(v, 0.0f);
            }
        }
        __syncthreads();

        // ====== fc2: 120 -> 84, relu. 84 threads, 4 images each ======
        if (tid < 84) {
            const int j = tid;
            const float* wr = sm + OFF_DW2T + j * DW2_STR;
            ull a0[4], a1[4];
            #pragma unroll
            for (int img = 0; img < 4; img++) { a0[img] = pack2(0.f, 0.f); a1[img] = a0[img]; }
            #pragma unroll 3
            for (int k = 0; k < 120; k += 4) {
                ulonglong2 wv = *reinterpret_cast<const ulonglong2*>(wr + k);
                #pragma unroll
                for (int img = 0; img < 4; img++) {
                    ulonglong2 av = *reinterpret_cast<const ulonglong2*>(
                        sm + OFF_FC1 + img * 120 + k);
                    FMA2(a0[img], av.x, wv.x, a0[img]);
                    FMA2(a1[img], av.y, wv.y, a1[img]);
                }
            }
            #pragma unroll
            for (int img = 0; img < 4; img++) {
                float2 s0 = unpack2(a0[img]), s1 = unpack2(a1[img]);
                float v = s0.x + s0.y + s1.x + s1.y + sm[OFF_DB2 + j];
                sm[OFF_FC2 + img * 88 + j] = fmaxf(v, 0.0f);
            }
        }
        __syncthreads();

        // =========== fc3: 84 -> 10. 40 threads ===========
        if (tid < 40) {
            const int j = tid >> 2, img = tid & 3;
            const float* act = sm + OFF_FC2 + img * 88;
            float acc = sm[OFF_DB3 + j];
            #pragma unroll 4
            for (int k = 0; k < 84; k++)
                acc = fmaf(act[k], sm[OFF_DW3 + k * 10 + j], acc);
            sm[OFF_LOG + img * 12 + j] = acc;
        }
        __syncthreads();

        // =========== softmax -> scratch. 4 threads ===========
        if (tid < 4 && base + tid < nimg) {
            const float* lg = sm + OFF_LOG + tid * 12;
            float mx = lg[0];
            #pragma unroll
            for (int j = 1; j < 10; j++) mx = fmaxf(mx, lg[j]);
            float e[10], s = 0.0f;
            #pragma unroll
            for (int j = 0; j < 10; j++) { e[j] = __expf(lg[j] - mx); s += e[j]; }
            float inv = 1.0f / s;
            float* po = g_probs + (size_t)(base + tid) * 10;
            #pragma unroll
            for (int j = 0; j < 10; j++) po[j] = e[j] * inv;
        }
        __syncthreads();
    }
}

// ---------------------------------------------------------------------------
// Kernel 2: Luhn DP (register-resident, high-MLP loads).
// ---------------------------------------------------------------------------
template <int N>
__device__ __forceinline__ float luhn_eval(const float* __restrict__ p)
{
    const int LUHN[10] = {0, 5, 1, 6, 2, 7, 3, 8, 4, 9};
    float4 v[(N * 10) / 4];
    const float4* pv = reinterpret_cast<const float4*>(p);
    #pragma unroll
    for (int i = 0; i < (N * 10) / 4; i++) v[i] = pv[i];
    float d[N * 10];
    #pragma unroll
    for (int i = 0; i < (N * 10) / 4; i++) {
        d[4 * i] = v[i].x; d[4 * i + 1] = v[i].y;
        d[4 * i + 2] = v[i].z; d[4 * i + 3] = v[i].w;
    }
    const int m = N - 1;
    float cur[10];
    #pragma unroll
    for (int j = 0; j < 10; j++)
        cur[j] = ((0 % 2) == (m % 2)) ? d[10 + LUHN[j]] : d[10 + j];
    #pragma unroll
    for (int i = 1; i < m; i++) {
        float dd[10];
        #pragma unroll
        for (int j = 0; j < 10; j++)
            dd[j] = ((i % 2) == (m % 2)) ? d[(i + 1) * 10 + LUHN[j]] : d[(i + 1) * 10 + j];
        float nxt[10];
        #pragma unroll
        for (int s = 0; s < 10; s++) nxt[s] = 0.0f;
        #pragma unroll
        for (int a = 0; a < 10; a++)
            #pragma unroll
            for (int q = 0; q < 10; q++)
                nxt[(a + q) % 10] = fmaf(cur[a], dd[q], nxt[(a + q) % 10]);
        #pragma unroll
        for (int s = 0; s < 10; s++) cur[s] = nxt[s];
    }
    float t10 = 0.0f;
    #pragma unroll
    for (int a = 1; a < 10; a++) t10 = fmaf(d[a], cur[10 - a], t10);
    return logf(t10);
}

__device__ float luhn_generic(const float* __restrict__ p, int n)
{
    const int LUHN[10] = {0, 5, 1, 6, 2, 7, 3, 8, 4, 9};
    const int m = n - 1;
    float cur[10];
    {
        const float* d = p + 10;
        bool perm = ((0 & 1) == (m & 1));
        #pragma unroll
        for (int j = 0; j < 10; j++) cur[j] = perm ? d[LUHN[j]] : d[j];
    }
    for (int i = 1; i < m; i++) {
        const float* d = p + (size_t)(i + 1) * 10;
        bool perm = ((i & 1) == (m & 1));
        float dd[10];
        #pragma unroll
        for (int j = 0; j < 10; j++) dd[j] = perm ? d[LUHN[j]] : d[j];
        float nxt[10];
        #pragma unroll
        for (int s = 0; s < 10; s++) nxt[s] = 0.0f;
        #pragma unroll
        for (int a = 0; a < 10; a++)
            #pragma unroll
            for (int q = 0; q < 10; q++)
                nxt[(a + q) % 10] = fmaf(cur[a], dd[q], nxt[(a + q) % 10]);
        #pragma unroll
        for (int s = 0; s < 10; s++) cur[s] = nxt[s];
    }
    float t10 = 0.0f;
    #pragma unroll
    for (int a = 1; a < 10; a++) t10 = fmaf(p[a], cur[10 - a], t10);
    return logf(t10);
}

__global__ void luhn_kernel(float* __restrict__ out, int B, int n)
{
    int b = blockIdx.x * blockDim.x + threadIdx.x;
    if (b >= B) return;
    const float* p = g_probs + (size_t)b * n * 10;
    if (n == 16) out[b] = luhn_eval<16>(p);
    else         out[b] = luhn_generic(p, n);
}

// ---------------------------------------------------------------------------
extern "C" void kernel_launch(void* const* d_in, const int* in_sizes, int n_in,
                              void* d_out, int out_size)
{
    const float* inputs = (const float*)d_in[0];
    const float* cw1    = (const float*)d_in[1];
    const float* cb1    = (const float*)d_in[2];
    const float* cw2    = (const float*)d_in[3];
    const float* cb2    = (const float*)d_in[4];
    const float* dw1    = (const float*)d_in[5];
    const float* db1    = (const float*)d_in[6];
    const float* dw2    = (const float*)d_in[7];
    const float* db2    = (const float*)d_in[8];
    const float* dw3    = (const float*)d_in[9];
    const float* db3    = (const float*)d_in[10];
    float* out = (float*)d_out;

    const int B = out_size;                      // 1024
    const int n = in_sizes[0] / (B * 784);       // 16
    const int nimg = B * n;

    const size_t smem_bytes = SMEM_FLOATS * sizeof(float);  // 229,136 B
    cudaFuncSetAttribute(cnn_kernel, cudaFuncAttributeMaxDynamicSharedMemorySize,
                         (int)smem_bytes);

    cnn_kernel<<<148, 512, smem_bytes>>>(inputs, cw1, cb1, cw2, cb2,
                                         dw1, db1, dw2, db2, dw3, db3, nimg);
    luhn_kernel<<<(B + 15) / 16, 16>>>(out, B, n);
}

// round 9
// speedup vs baseline: 1.0873x; 1.0873x over previous
#include <cuda_runtime.h>
#include <math.h>

typedef unsigned long long ull;

// ---------------------------------------------------------------------------
// packed fp32x2 helpers (Blackwell FFMA2)
// ---------------------------------------------------------------------------
#define FMA2(d, a, b, c) \
    asm("fma.rn.f32x2 %0, %1, %2, %3;" : "=l"(d) : "l"(a), "l"(b), "l"(c))

static __device__ __forceinline__ ull pack2(float lo, float hi) {
    ull r; asm("mov.b64 %0, {%1, %2};" : "=l"(r) : "f"(lo), "f"(hi)); return r;
}
static __device__ __forceinline__ float2 unpack2(ull v) {
    float2 r; asm("mov.b64 {%0, %1}, %2;" : "=f"(r.x), "=f"(r.y) : "l"(v)); return r;
}
static __device__ __forceinline__ ull lds64(const float* p) {
    return *reinterpret_cast<const ull*>(p);
}

// Scratch: per-image softmax probabilities (1024 batches * 16 digits * 10)
__device__ float g_probs[1024 * 16 * 10];

// ---------------------------------------------------------------------------
// shared memory layout (float offsets)
// ---------------------------------------------------------------------------
#define OFF_DW1T  0        // [120][260]  transposed dw1, 16B-aligned rows
#define DW1_STR   260
#define OFF_DW2T  31200    // [84][124]   transposed dw2, 16B-aligned rows
#define DW2_STR   124
#define OFF_DW3   41616    // 840
#define OFF_W1P   42456    // [25][8]  conv1 weights, 6 ch + 2 pad per tap
#define OFF_W2X   42656    // 2400 interleaved conv2 weights
#define OFF_B1    45056    // 8
#define OFF_B2    45064    // 16
#define OFF_DB1   45080    // 120
#define OFF_DB2   45200    // 88
#define OFF_DB3   45288    // 12
#define OFF_IMG   45300    // [4][784]
#define OFF_P1T   48436    // [4][6][12][24]  pooled conv1, dup pairs
#define P1_IMG_STR 1728
#define OFF_P2    55348    // [4][264]
#define P2_STR    264
#define OFF_FC1   56404    // [4][120]
#define OFF_FC2   56884    // [4][88]
#define OFF_LOG   57236    // [4][12]
#define SMEM_FLOATS 57284  // = 229,136 bytes

#define HBAR(h) asm volatile("bar.sync %0, 256;" :: "r"((h) + 1) : "memory")

// ---------------------------------------------------------------------------
// Phase bodies (shared between both halves; noinline keeps one I$ copy).
// t = thread index within half (0..255). slot = image slot base (0 or 2).
// ---------------------------------------------------------------------------
__device__ __noinline__ void do_conv1(float* sm, int t, int slot)
{
    if (t >= 144) return;
    const int im  = t / 72;
    const int r72 = t % 72;
    const int py = r72 / 6, xg = r72 % 6, x0 = 4 * xg;
    const float* ibase = sm + OFF_IMG + (slot + im) * 784 + 2 * py * 28 + x0;
    float* s_p1 = sm + OFF_P1T + (slot + im) * P1_IMG_STR;

    ull bp[3];
    #pragma unroll
    for (int cp = 0; cp < 3; cp++)
        bp[cp] = pack2(sm[OFF_B1 + 2 * cp], sm[OFF_B1 + 2 * cp + 1]);
    ull acc[2][4][3];
    #pragma unroll
    for (int dy = 0; dy < 2; dy++)
        #pragma unroll
        for (int dx = 0; dx < 4; dx++)
            #pragma unroll
            for (int cp = 0; cp < 3; cp++) acc[dy][dx][cp] = bp[cp];

    #pragma unroll
    for (int r = 0; r < 6; r++) {
        float4 v0 = *reinterpret_cast<const float4*>(ibase + r * 28);
        float4 v1 = *reinterpret_cast<const float4*>(ibase + r * 28 + 4);
        ull ap[8];
        ap[0] = pack2(v0.x, v0.x); ap[1] = pack2(v0.y, v0.y);
        ap[2] = pack2(v0.z, v0.z); ap[3] = pack2(v0.w, v0.w);
        ap[4] = pack2(v1.x, v1.x); ap[5] = pack2(v1.y, v1.y);
        ap[6] = pack2(v1.z, v1.z); ap[7] = pack2(v1.w, v1.w);
        #pragma unroll
        for (int dy = 0; dy < 2; dy++) {
            const int ky = r - dy;
            if (ky < 0 || ky > 4) continue;
            #pragma unroll
            for (int kx = 0; kx < 5; kx++) {
                const float* wp = sm + OFF_W1P + (ky * 5 + kx) * 8;
                ulonglong2 w01 = *reinterpret_cast<const ulonglong2*>(wp);
                ull w2 = lds64(wp + 4);
                #pragma unroll
                for (int dx = 0; dx < 4; dx++) {
                    FMA2(acc[dy][dx][0], ap[kx + dx], w01.x, acc[dy][dx][0]);
                    FMA2(acc[dy][dx][1], ap[kx + dx], w01.y, acc[dy][dx][1]);
                    FMA2(acc[dy][dx][2], ap[kx + dx], w2,    acc[dy][dx][2]);
                }
            }
        }
    }
    #pragma unroll
    for (int cp = 0; cp < 3; cp++) {
        #pragma unroll
        for (int dxp = 0; dxp < 2; dxp++) {
            float2 a0 = unpack2(acc[0][2 * dxp][cp]);
            float2 a1 = unpack2(acc[0][2 * dxp + 1][cp]);
            float2 b0 = unpack2(acc[1][2 * dxp][cp]);
            float2 b1 = unpack2(acc[1][2 * dxp + 1][cp]);
            float m0 = fmaxf(fmaxf(fmaxf(a0.x, a1.x), fmaxf(b0.x, b1.x)), 0.0f);
            float m1 = fmaxf(fmaxf(fmaxf(a0.y, a1.y), fmaxf(b0.y, b1.y)), 0.0f);
            const int px = 2 * xg + dxp;
            *reinterpret_cast<ull*>(s_p1 + ((2 * cp)     * 12 + py) * 24 + 2 * px) = pack2(m0, m0);
            *reinterpret_cast<ull*>(s_p1 + ((2 * cp + 1) * 12 + py) * 24 + 2 * px) = pack2(m1, m1);
        }
    }
}

__device__ __noinline__ void do_conv2(float* sm, int t, int slot)
{
    // caller guarantees t < 128. thread = (im, py 0..3, xg 0..1, cg 0..7)
    const int im = t >> 6;
    const int u  = t & 63;
    const int py = u >> 4, xg = (u >> 3) & 1, cg = u & 7;
    const int x0 = 4 * xg;
    const float* base0 = sm + OFF_P1T + (slot + im) * P1_IMG_STR + 2 * py * 24 + 2 * x0;
    const float* wbase = sm + OFF_W2X + cg * 4;

    ull bp = lds64(sm + OFF_B2 + 2 * cg);
    ull acc[2][4];
    #pragma unroll
    for (int dy = 0; dy < 2; dy++)
        #pragma unroll
        for (int dx = 0; dx < 4; dx++) acc[dy][dx] = bp;

    #pragma unroll
    for (int r = 0; r < 6; r++) {
        #pragma unroll
        for (int ip = 0; ip < 3; ip++) {
            const float* r0 = base0 + (2 * ip) * 288 + r * 24;
            const float* r1 = r0 + 288;
            ulonglong2 a00 = *reinterpret_cast<const ulonglong2*>(r0);
            ulonglong2 a01 = *reinterpret_cast<const ulonglong2*>(r0 + 4);
            ulonglong2 a02 = *reinterpret_cast<const ulonglong2*>(r0 + 8);
            ulonglong2 a03 = *reinterpret_cast<const ulonglong2*>(r0 + 12);
            ulonglong2 a10 = *reinterpret_cast<const ulonglong2*>(r1);
            ulonglong2 a11 = *reinterpret_cast<const ulonglong2*>(r1 + 4);
            ulonglong2 a12 = *reinterpret_cast<const ulonglong2*>(r1 + 8);
            ulonglong2 a13 = *reinterpret_cast<const ulonglong2*>(r1 + 12);
            ull ap0[8] = {a00.x, a00.y, a01.x, a01.y, a02.x, a02.y, a03.x, a03.y};
            ull ap1[8] = {a10.x, a10.y, a11.x, a11.y, a12.x, a12.y, a13.x, a13.y};
            #pragma unroll
            for (int dy = 0; dy < 2; dy++) {
                const int ky = r - dy;
                if (ky < 0 || ky > 4) continue;
                #pragma unroll
                for (int kx = 0; kx < 5; kx++) {
                    ulonglong2 w = *reinterpret_cast<const ulonglong2*>(
                        wbase + ((ky * 5 + kx) * 3 + ip) * 32);
                    #pragma unroll
                    for (int dx = 0; dx < 4; dx++) {
                        FMA2(acc[dy][dx], ap0[kx + dx], w.x, acc[dy][dx]);
                        FMA2(acc[dy][dx], ap1[kx + dx], w.y, acc[dy][dx]);
                    }
                }
            }
        }
    }
    float* s_p2 = sm + OFF_P2 + (slot + im) * P2_STR;
    #pragma unroll
    for (int dxp = 0; dxp < 2; dxp++) {
        float2 a0 = unpack2(acc[0][2 * dxp]);
        float2 a1 = unpack2(acc[0][2 * dxp + 1]);
        float2 b0 = unpack2(acc[1][2 * dxp]);
        float2 b1 = unpack2(acc[1][2 * dxp + 1]);
        float m0 = fmaxf(fmaxf(fmaxf(a0.x, a1.x), fmaxf(b0.x, b1.x)), 0.0f);
        float m1 = fmaxf(fmaxf(fmaxf(a0.y, a1.y), fmaxf(b0.y, b1.y)), 0.0f);
        const int px = 2 * xg + dxp;
        *reinterpret_cast<ull*>(s_p2 + (py * 4 + px) * 16 + 2 * cg) = pack2(m0, m1);
    }
}

static __device__ __forceinline__ void do_fc1(float* sm, int t, int slot)
{
    if (t >= 240) return;
    const int j = t >> 1, im = t & 1;
    const float* act = sm + OFF_P2 + (slot + im) * P2_STR;
    const float* wr  = sm + OFF_DW1T + j * DW1_STR;
    ull acc0 = pack2(0.0f, 0.0f), acc1 = pack2(0.0f, 0.0f);
    #pragma unroll 8
    for (int k = 0; k < 256; k += 4) {
        ulonglong2 av = *reinterpret_cast<const ulonglong2*>(act + k);
        ulonglong2 wv = *reinterpret_cast<const ulonglong2*>(wr + k);
        FMA2(acc0, av.x, wv.x, acc0);
        FMA2(acc1, av.y, wv.y, acc1);
    }
    float2 s0 = unpack2(acc0), s1 = unpack2(acc1);
    float v = s0.x + s0.y + s1.x + s1.y + sm[OFF_DB1 + j];
    sm[OFF_FC1 + (slot + im) * 120 + j] = fmaxf(v, 0.0f);
}

static __device__ __forceinline__ void do_fc2(float* sm, int t, int slot)
{
    if (t >= 168) return;
    const int j = t >> 1, im = t & 1;
    const float* act = sm + OFF_FC1 + (slot + im) * 120;
    const float* wr  = sm + OFF_DW2T + j * DW2_STR;
    ull acc0 = pack2(0.0f, 0.0f), acc1 = pack2(0.0f, 0.0f);
    #pragma unroll 6
    for (int k = 0; k < 120; k += 4) {
        ulonglong2 av = *reinterpret_cast<const ulonglong2*>(act + k);
        ulonglong2 wv = *reinterpret_cast<const ulonglong2*>(wr + k);
        FMA2(acc0, av.x, wv.x, acc0);
        FMA2(acc1, av.y, wv.y, acc1);
    }
    float2 s0 = unpack2(acc0), s1 = unpack2(acc1);
    float v = s0.x + s0.y + s1.x + s1.y + sm[OFF_DB2 + j];
    sm[OFF_FC2 + (slot + im) * 88 + j] = fmaxf(v, 0.0f);
}

static __device__ __forceinline__ void do_fc3(float* sm, int t, int slot)
{
    if (t >= 20) return;
    const int j = t >> 1, im = t & 1;
    const float* act = sm + OFF_FC2 + (slot + im) * 88;
    float acc = sm[OFF_DB3 + j];
    #pragma unroll 4
    for (int k = 0; k < 84; k++)
        acc = fmaf(act[k], sm[OFF_DW3 + k * 10 + j], acc);
    sm[OFF_LOG + (slot + im) * 12 + j] = acc;
}

static __device__ __forceinline__ void do_softmax(float* sm, int t, int slot,
                                                  int base, int nimg)
{
    if (t >= 2) return;
    const int img = base + slot + t;
    if (img >= nimg) return;
    const float* lg = sm + OFF_LOG + (slot + t) * 12;
    float mx = lg[0];
    #pragma unroll
    for (int j = 1; j < 10; j++) mx = fmaxf(mx, lg[j]);
    float e[10], s = 0.0f;
    #pragma unroll
    for (int j = 0; j < 10; j++) { e[j] = __expf(lg[j] - mx); s += e[j]; }
    float inv = 1.0f / s;
    float* po = g_probs + (size_t)img * 10;
    #pragma unroll
    for (int j = 0; j < 10; j++) po[j] = e[j] * inv;
}

static __device__ __forceinline__ void do_prefetch(float* sm, int t, int slot,
                                                   const float* inputs,
                                                   int nb, int nimg)
{
    // threads t in [128,256): copy this half's next 2 images
    const int i0 = t - 128;
    if (nb + slot < nimg) {
        const float4* iv = reinterpret_cast<const float4*>(inputs + (size_t)(nb + slot) * 784);
        float4* ov = reinterpret_cast<float4*>(sm + OFF_IMG + slot * 784);
        for (int i = i0; i < 196; i += 128) ov[i] = iv[i];
    }
    if (nb + slot + 1 < nimg) {
        const float4* iv = reinterpret_cast<const float4*>(inputs + (size_t)(nb + slot + 1) * 784);
        float4* ov = reinterpret_cast<float4*>(sm + OFF_IMG + (slot + 1) * 784);
        for (int i = i0; i < 196; i += 128) ov[i] = iv[i];
    }
}

// ---------------------------------------------------------------------------
// Kernel 1: persistent fused LeNet. 148 CTAs x 512 threads; two independent
// 256-thread halves (warps 0-7 / 8-15), each pipelining 2 images with the
// round-6 phase mappings; half B runs a rotated phase order with a one-time
// offset so the two streams' phases interleave on every SMSP.
// ---------------------------------------------------------------------------
__global__ void __launch_bounds__(512, 1) cnn_kernel(
    const float* __restrict__ inputs,
    const float* __restrict__ cw1, const float* __restrict__ cb1,
    const float* __restrict__ cw2, const float* __restrict__ cb2,
    const float* __restrict__ dw1, const float* __restrict__ db1,
    const float* __restrict__ dw2, const float* __restrict__ db2,
    const float* __restrict__ dw3, const float* __restrict__ db3,
    int nimg)
{
    extern __shared__ float sm[];
    const int tid = threadIdx.x;

    // ---- one-time weight staging ----
    for (int idx = tid; idx < 256 * 120; idx += 512) {
        int k = idx / 120, j = idx % 120;
        sm[OFF_DW1T + j * DW1_STR + k] = dw1[idx];
    }
    for (int idx = tid; idx < 120 * 84; idx += 512) {
        int k = idx / 84, j = idx % 84;
        sm[OFF_DW2T + j * DW2_STR + k] = dw2[idx];
    }
    for (int idx = tid; idx < 840; idx += 512) sm[OFF_DW3 + idx] = dw3[idx];
    for (int idx = tid; idx < 150; idx += 512) {
        int pk = idx / 6, c = idx % 6;
        sm[OFF_W1P + pk * 8 + c] = cw1[idx];
    }
    for (int idx = tid; idx < 2400; idx += 512) {
        int p = idx >> 4, ch = idx & 15;
        int pk = p / 6, i = p % 6;
        sm[OFF_W2X + (pk * 3 + (i >> 1)) * 32 + (ch >> 1) * 4 + (i & 1) * 2 + (ch & 1)]
            = cw2[idx];
    }
    if (tid < 6)   sm[OFF_B1  + tid] = cb1[tid];
    if (tid < 16)  sm[OFF_B2  + tid] = cb2[tid];
    if (tid < 120) sm[OFF_DB1 + tid] = db1[tid];
    if (tid < 84)  sm[OFF_DB2 + tid] = db2[tid];
    if (tid < 10)  sm[OFF_DB3 + tid] = db3[tid];

    // ---- prologue: load first batch of 4 images (guarded per image) ----
    {
        const int b0 = blockIdx.x * 4;
        #pragma unroll
        for (int k = 0; k < 4; k++) {
            if (b0 + k < nimg) {
                const float4* iv = reinterpret_cast<const float4*>(inputs + (size_t)(b0 + k) * 784);
                float4* ov = reinterpret_cast<float4*>(sm + OFF_IMG + k * 784);
                for (int i = tid; i < 196; i += 512) ov[i] = iv[i];
            }
        }
    }
    __syncthreads();

    const int h    = tid >> 8;       // half 0/1 (warps 0-7 / 8-15)
    const int t    = tid & 255;      // thread within half
    const int qstep = gridDim.x * 4;

    if (h == 0) {
        // ---- half A: c1, c2+pref, fc1, fc2, fc3, softmax ----
        for (int base = blockIdx.x * 4; base < nimg; base += qstep) {
            do_conv1(sm, t, 0);
            HBAR(0);
            if (t < 128) do_conv2(sm, t, 0);
            else         do_prefetch(sm, t, 0, inputs, base + qstep, nimg);
            HBAR(0);
            do_fc1(sm, t, 0); HBAR(0);
            do_fc2(sm, t, 0); HBAR(0);
            do_fc3(sm, t, 0); HBAR(0);
            do_softmax(sm, t, 0, base, nimg); HBAR(0);
        }
    } else {
        // ---- half B: conv1 prologue (+1 redundant recompute = phase offset),
        //      then rotated order: c2+pref, fc1, fc2, fc3, softmax, c1(next) ----
        do_conv1(sm, t, 2);
        HBAR(1);
        do_conv1(sm, t, 2);   // deliberate recompute: shifts B ~1/3 phase vs A
        HBAR(1);
        for (int base = blockIdx.x * 4; base < nimg; base += qstep) {
            if (t < 128) do_conv2(sm, t, 2);
            else         do_prefetch(sm, t, 2, inputs, base + qstep, nimg);
            HBAR(1);
            do_fc1(sm, t, 2); HBAR(1);
            do_fc2(sm, t, 2); HBAR(1);
            do_fc3(sm, t, 2); HBAR(1);
            do_softmax(sm, t, 2, base, nimg); HBAR(1);
            if (base + qstep < nimg) do_conv1(sm, t, 2);
            HBAR(1);
        }
    }
}

// ---------------------------------------------------------------------------
// Kernel 2: Luhn DP (register-resident, high-MLP loads). Full warps.
// ---------------------------------------------------------------------------
template <int N>
__device__ __forceinline__ float luhn_eval(const float* __restrict__ p)
{
    const int LUHN[10] = {0, 5, 1, 6, 2, 7, 3, 8, 4, 9};
    float4 v[(N * 10) / 4];
    const float4* pv = reinterpret_cast<const float4*>(p);
    #pragma unroll
    for (int i = 0; i < (N * 10) / 4; i++) v[i] = pv[i];
    float d[N * 10];
    #pragma unroll
    for (int i = 0; i < (N * 10) / 4; i++) {
        d[4 * i] = v[i].x; d[4 * i + 1] = v[i].y;
        d[4 * i + 2] = v[i].z; d[4 * i + 3] = v[i].w;
    }
    const int m = N - 1;
    float cur[10];
    #pragma unroll
    for (int j = 0; j < 10; j++)
        cur[j] = ((0 % 2) == (m % 2)) ? d[10 + LUHN[j]] : d[10 + j];
    #pragma unroll
    for (int i = 1; i < m; i++) {
        float dd[10];
        #pragma unroll
        for (int j = 0; j < 10; j++)
            dd[j] = ((i % 2) == (m % 2)) ? d[(i + 1) * 10 + LUHN[j]] : d[(i + 1) * 10 + j];
        float nxt[10];
        #pragma unroll
        for (int s = 0; s < 10; s++) nxt[s] = 0.0f;
        #pragma unroll
        for (int a = 0; a < 10; a++)
            #pragma unroll
            for (int q = 0; q < 10; q++)
                nxt[(a + q) % 10] = fmaf(cur[a], dd[q], nxt[(a + q) % 10]);
        #pragma unroll
        for (int s = 0; s < 10; s++) cur[s] = nxt[s];
    }
    float t10 = 0.0f;
    #pragma unroll
    for (int a = 1; a < 10; a++) t10 = fmaf(d[a], cur[10 - a], t10);
    return logf(t10);
}

__device__ float luhn_generic(const float* __restrict__ p, int n)
{
    const int LUHN[10] = {0, 5, 1, 6, 2, 7, 3, 8, 4, 9};
    const int m = n - 1;
    float cur[10];
    {
        const float* d = p + 10;
        bool perm = ((0 & 1) == (m & 1));
        #pragma unroll
        for (int j = 0; j < 10; j++) cur[j] = perm ? d[LUHN[j]] : d[j];
    }
    for (int i = 1; i < m; i++) {
        const float* d = p + (size_t)(i + 1) * 10;
        bool perm = ((i & 1) == (m & 1));
        float dd[10];
        #pragma unroll
        for (int j = 0; j < 10; j++) dd[j] = perm ? d[LUHN[j]] : d[j];
        float nxt[10];
        #pragma unroll
        for (int s = 0; s < 10; s++) nxt[s] = 0.0f;
        #pragma unroll
        for (int a = 0; a < 10; a++)
            #pragma unroll
            for (int q = 0; q < 10; q++)
                nxt[(a + q) % 10] = fmaf(cur[a], dd[q], nxt[(a + q) % 10]);
        #pragma unroll
        for (int s = 0; s < 10; s++) cur[s] = nxt[s];
    }
    float t10 = 0.0f;
    #pragma unroll
    for (int a = 1; a < 10; a++) t10 = fmaf(p[a], cur[10 - a], t10);
    return logf(t10);
}

__global__ void luhn_kernel(float* __restrict__ out, int B, int n)
{
    int b = blockIdx.x * blockDim.x + threadIdx.x;
    if (b >= B) return;
    const float* p = g_probs + (size_t)b * n * 10;
    if (n == 16) out[b] = luhn_eval<16>(p);
    else         out[b] = luhn_generic(p, n);
}

// ---------------------------------------------------------------------------
extern "C" void kernel_launch(void* const* d_in, const int* in_sizes, int n_in,
                              void* d_out, int out_size)
{
    const float* inputs = (const float*)d_in[0];
    const float* cw1    = (const float*)d_in[1];
    const float* cb1    = (const float*)d_in[2];
    const float* cw2    = (const float*)d_in[3];
    const float* cb2    = (const float*)d_in[4];
    const float* dw1    = (const float*)d_in[5];
    const float* db1    = (const float*)d_in[6];
    const float* dw2    = (const float*)d_in[7];
    const float* db2    = (const float*)d_in[8];
    const float* dw3    = (const float*)d_in[9];
    const float* db3    = (const float*)d_in[10];
    float* out = (float*)d_out;

    const int B = out_size;                      // 1024
    const int n = in_sizes[0] / (B * 784);       // 16
    const int nimg = B * n;

    const size_t smem_bytes = SMEM_FLOATS * sizeof(float);  // 229,136 B
    cudaFuncSetAttribute(cnn_kernel, cudaFuncAttributeMaxDynamicSharedMemorySize,
                         (int)smem_bytes);

    cnn_kernel<<<148, 512, smem_bytes>>>(inputs, cw1, cb1, cw2, cb2,
                                         dw1, db1, dw2, db2, dw3, db3, nimg);
    luhn_kernel<<<(B + 127) / 128, 128>>>(out, B, n);
}